// round 11
// baseline (speedup 1.0000x reference)
#include <cuda_runtime.h>
#include <cuda_fp16.h>
#include <cstdint>
#include <math.h>

#define BSZ 1024
#define DIM 128
#define K2  256     // concatenated feature length
#define PITCH 264   // global row pitch in fp16 (528 B; 528 % 128 == 16 -> LDSM conflict-free)

// ---------------- scratch (__device__ globals; allocation-free rule) -------
__device__ __align__(16) __half gZp[BSZ * PITCH];  // padded [s1*x | s2*exp(1-dc)]
__device__ float gC[BSZ];                          // (1-a)*||x_i||^2
__device__ int   gDone[256];                       // per-CTA prep flags

// ---------------- helpers --------------------------------------------------
__device__ __forceinline__ uint32_t smem_u32(const void* p) {
    uint32_t a;
    asm("{ .reg .u64 t; cvta.to.shared.u64 t, %1; cvt.u32.u64 %0, t; }"
        : "=r"(a) : "l"(p));
    return a;
}
#define LDSM4(r0, r1, r2, r3, addr) \
    asm volatile("ldmatrix.sync.aligned.m8n8.x4.shared.b16 {%0,%1,%2,%3}, [%4];" \
                 : "=r"(r0), "=r"(r1), "=r"(r2), "=r"(r3) : "r"(addr))
#define MBARRIER_INIT(addr, cnt) \
    asm volatile("mbarrier.init.shared.b64 [%0], %1;" :: "r"(addr), "r"(cnt) : "memory")
#define MBARRIER_EXPECT_TX(addr, bytes) \
    asm volatile("mbarrier.arrive.expect_tx.shared.b64 _, [%0], %1;" \
                 :: "r"(addr), "r"((uint32_t)(bytes)) : "memory")
#define BULK_G2S(dst, src, bytes, mbar) \
    asm volatile("cp.async.bulk.shared::cta.global.mbarrier::complete_tx::bytes " \
                 "[%0], [%1], %2, [%3];" \
                 :: "r"(dst), "l"(src), "r"((uint32_t)(bytes)), "r"(mbar) : "memory")
#define MBARRIER_WAIT_PARITY(addr, par) do {                                      \
    uint32_t _m = (addr), _p = (par), _d;                                         \
    asm volatile("{\n\t.reg .pred p;\n\t"                                         \
        "mbarrier.try_wait.parity.acquire.cta.shared::cta.b64 p, [%1], %2;\n\t"   \
        "selp.b32 %0, 1, 0, p;\n\t}" : "=r"(_d) : "r"(_m), "r"(_p) : "memory");   \
    if (!_d) {                                                                    \
        asm volatile("{\n\t.reg .pred P1;\n\t"                                    \
            "WL_%=:\n\t"                                                          \
            "mbarrier.try_wait.parity.acquire.cta.shared::cta.b64 P1, [%0], %1, 0x989680;\n\t" \
            "@P1 bra.uni WD_%=;\n\tbra.uni WL_%=;\n\tWD_%=:\n\t}"                 \
            :: "r"(_m), "r"(_p) : "memory");                                      \
    }                                                                             \
} while (0)

__device__ __forceinline__ void mma_f16(float c[4],
                                        uint32_t a0, uint32_t a1, uint32_t a2, uint32_t a3,
                                        uint32_t b0, uint32_t b1) {
    asm volatile(
        "mma.sync.aligned.m16n8k16.row.col.f32.f16.f16.f32 "
        "{%0,%1,%2,%3}, {%4,%5,%6,%7}, {%8,%9}, {%0,%1,%2,%3};"
        : "+f"(c[0]), "+f"(c[1]), "+f"(c[2]), "+f"(c[3])
        : "r"(a0), "r"(a1), "r"(a2), "r"(a3), "r"(b0), "r"(b1));
}

// ---------------------------------------------------------------------------
// Fused kernel: prep (4 rows/CTA) + flag handshake + bulk-DMA staged
// 64x64 fp16 tensor-core GEMM + epilogue.
// grid (16,16)=256 CTAs, 256 threads, 2 CTAs/SM (all co-resident).
//   smem: A @0 (64*528=33792) | B @33792 ; 67584 B dynamic.
// ---------------------------------------------------------------------------
#define ROWB   528
#define OFF_B  33792
#define A_HALF 16896    // 32 rows
#define B_QUAR 8448     // 16 rows
#define SMEM_BYTES 67584

__global__ void __launch_bounds__(256, 2)
fused_kernel(const float* __restrict__ x, const float* __restrict__ dc,
             const float* __restrict__ ap, float* __restrict__ out) {
    extern __shared__ __align__(16) char smem[];
    __shared__ __align__(8) uint64_t s_mbar[6];   // A halves: 0,1 ; B quarters: 2..5

    const int tid = threadIdx.x;
    const int wid = tid >> 5;
    const int lid = tid & 31;
    const int wm  = wid & 1;           // m offset wm*32
    const int wn  = wid >> 1;          // n offset wn*16
    const int i0  = blockIdx.y * 64;
    const int j0  = blockIdx.x * 64;
    const int bid = blockIdx.y * 16 + blockIdx.x;
    const uint32_t sb = smem_u32(smem);
    const uint32_t mb = smem_u32(s_mbar);

    // ---- init: mbarriers + own-flag reset ----
    if (tid == 0) {
#pragma unroll
        for (int s = 0; s < 6; s++) MBARRIER_INIT(mb + 8 * s, 1);
        *(volatile int*)&gDone[bid] = 0;
    }

    // ---- prep: rows 4*bid .. 4*bid+3 (32 threads per row, threads 0-127) --
    if (tid < 128) {
        const int row = 4 * bid + (tid >> 5);
        const int d   = (tid & 31) * 4;
        const float a  = ap[0];
        const float s1 = sqrtf(2.0f * (1.0f - a));
        const float s2 = sqrtf(a);

        const float4 xv = *(const float4*)&x[row * DIM + d];
        const float4 dv = *(const float4*)&dc[row * DIM + d];

        __half zb[4] = { __float2half_rn(s1 * xv.x), __float2half_rn(s1 * xv.y),
                         __float2half_rn(s1 * xv.z), __float2half_rn(s1 * xv.w) };
        __half hb[4] = { __float2half_rn(s2 * __expf(1.0f - dv.x)),
                         __float2half_rn(s2 * __expf(1.0f - dv.y)),
                         __float2half_rn(s2 * __expf(1.0f - dv.z)),
                         __float2half_rn(s2 * __expf(1.0f - dv.w)) };

        const int ob = row * PITCH + d;
        *(uint2*)&gZp[ob]       = *(uint2*)zb;
        *(uint2*)&gZp[ob + DIM] = *(uint2*)hb;

        float s = xv.x * xv.x + xv.y * xv.y + xv.z * xv.z + xv.w * xv.w;
#pragma unroll
        for (int o = 16; o; o >>= 1) s += __shfl_down_sync(0xffffffffu, s, o);
        if ((tid & 31) == 0) gC[row] = (1.0f - a) * s;
    }
    __threadfence();
    __syncthreads();
    if (tid == 0) *(volatile int*)&gDone[bid] = 1;

    // ---- wait for the 32 producer CTAs covering rows [i0,i0+64) u [j0,j0+64)
    if (tid < 16) {
        volatile int* f = &gDone[(i0 >> 2) + tid];
        while (*f == 0) { __nanosleep(40); }
    } else if (tid < 32) {
        volatile int* f = &gDone[(j0 >> 2) + (tid - 16)];
        while (*f == 0) { __nanosleep(40); }
    }
    __syncthreads();

    // ---- stage tiles: 6 bulk ops, per-warp-visible completion ----
    if (tid == 0) {
        asm volatile("fence.proxy.async;" ::: "memory");
        MBARRIER_EXPECT_TX(mb,      A_HALF);
        BULK_G2S(sb,                gZp + (size_t)i0 * PITCH,        A_HALF, mb);
        MBARRIER_EXPECT_TX(mb + 16, B_QUAR);
        BULK_G2S(sb + OFF_B,        gZp + (size_t)j0 * PITCH,        B_QUAR, mb + 16);
        MBARRIER_EXPECT_TX(mb + 24, B_QUAR);
        BULK_G2S(sb + OFF_B + B_QUAR, gZp + (size_t)(j0 + 16) * PITCH, B_QUAR, mb + 24);
        MBARRIER_EXPECT_TX(mb + 32, B_QUAR);
        BULK_G2S(sb + OFF_B + 2 * B_QUAR, gZp + (size_t)(j0 + 32) * PITCH, B_QUAR, mb + 32);
        MBARRIER_EXPECT_TX(mb + 40, B_QUAR);
        BULK_G2S(sb + OFF_B + 3 * B_QUAR, gZp + (size_t)(j0 + 48) * PITCH, B_QUAR, mb + 40);
        MBARRIER_EXPECT_TX(mb + 8,  A_HALF);
        BULK_G2S(sb + A_HALF,       gZp + (size_t)(i0 + 32) * PITCH, A_HALF, mb + 8);
    }

    // ---- per-lane ldmatrix base addresses ----
    const uint32_t arow = lid & 15;
    const uint32_t acol = (lid >> 4) * 16;            // bytes
    const uint32_t brow = (lid & 7) | (((lid >> 4) & 1) << 3);
    const uint32_t bcol = ((lid >> 3) & 1) * 16;
    const uint32_t aAd = sb + (wm * 32 + arow) * ROWB + acol;
    const uint32_t bAd = sb + OFF_B + (wn * 16 + brow) * ROWB + bcol;

    float acc[2][2][4] = {};
    uint32_t F[2][12];   // [set][ a0..7 | b0..3 ]

    auto ldf = [&](uint32_t* f, int ks) {
        const uint32_t ko = (uint32_t)ks * 32;
        LDSM4(f[0], f[1], f[2],  f[3],  aAd + ko);
        LDSM4(f[4], f[5], f[6],  f[7],  aAd + ko + 16 * ROWB);
        LDSM4(f[8], f[9], f[10], f[11], bAd + ko);
        if (ks < 8) {   // W's first K-half is -Z: negate A frags (packed fp16)
#pragma unroll
            for (int q = 0; q < 8; q++) f[q] ^= 0x80008000u;
        }
    };
    auto domma = [&](uint32_t* f) {
#pragma unroll
        for (int mf = 0; mf < 2; mf++) {
            uint32_t* a = f + mf * 4;
#pragma unroll
            for (int nf = 0; nf < 2; nf++)
                mma_f16(acc[mf][nf], a[0], a[1], a[2], a[3],
                        f[8 + nf * 2], f[9 + nf * 2]);
        }
    };

    // ---- wait only on own A-half + B-quarter, then 16 k-steps ----
    MBARRIER_WAIT_PARITY(mb + 8 * wm, 0);
    MBARRIER_WAIT_PARITY(mb + 16 + 8 * wn, 0);

    ldf(F[0], 0);
#pragma unroll
    for (int ks = 0; ks < 15; ks++) {
        ldf(F[(ks + 1) & 1], ks + 1);
        domma(F[ks & 1]);
    }
    domma(F[1]);

    // ---- epilogue: out[i][j] = (i==j) ? 1 : DIM / (c_i + c_j + S_ij) ----
    const int g = lid >> 2;
    const int t = lid & 3;
#pragma unroll
    for (int mf = 0; mf < 2; mf++) {
        const int ia = i0 + wm * 32 + mf * 16 + g;
        const int ib = ia + 8;
        const float cia = gC[ia];
        const float cib = gC[ib];
#pragma unroll
        for (int nf = 0; nf < 2; nf++) {
            const int j = j0 + wn * 16 + nf * 8 + t * 2;
            const float cj0 = gC[j];
            const float cj1 = gC[j + 1];
            const float* s = acc[mf][nf];

            float v00 = (ia == j)     ? 1.0f : __fdividef((float)DIM, cia + cj0 + s[0]);
            float v01 = (ia == j + 1) ? 1.0f : __fdividef((float)DIM, cia + cj1 + s[1]);
            float v10 = (ib == j)     ? 1.0f : __fdividef((float)DIM, cib + cj0 + s[2]);
            float v11 = (ib == j + 1) ? 1.0f : __fdividef((float)DIM, cib + cj1 + s[3]);

            *(float2*)&out[ia * BSZ + j] = make_float2(v00, v01);
            *(float2*)&out[ib * BSZ + j] = make_float2(v10, v11);
        }
    }
}

// ---------------------------------------------------------------------------
extern "C" void kernel_launch(void* const* d_in, const int* in_sizes, int n_in,
                              void* d_out, int out_size) {
    const float* x  = (const float*)d_in[0];
    const float* dc = (const float*)d_in[1];
    const float* ap = (const float*)d_in[2];
    float* out = (float*)d_out;

    cudaFuncSetAttribute(fused_kernel, cudaFuncAttributeMaxDynamicSharedMemorySize, SMEM_BYTES);
    fused_kernel<<<dim3(16, 16), 256, SMEM_BYTES>>>(x, dc, ap, out);
}

// round 12
// speedup vs baseline: 1.6386x; 1.6386x over previous
#include <cuda_runtime.h>
#include <cuda_fp16.h>
#include <cstdint>
#include <math.h>

#define BSZ 1024
#define DIM 128
#define K2  256     // concatenated feature length
#define PITCH 264   // global row pitch in fp16 (528 B; 528 % 128 == 16 -> LDSM conflict-free)

// ---------------- scratch (__device__ globals; allocation-free rule) -------
__device__ __align__(16) __half gZp[BSZ * PITCH];  // padded [s1*x | s2*exp(1-dc)]
__device__ float gC[BSZ];                          // (1-a)*||x_i||^2

// ---------------- helpers --------------------------------------------------
__device__ __forceinline__ uint32_t smem_u32(const void* p) {
    uint32_t a;
    asm("{ .reg .u64 t; cvta.to.shared.u64 t, %1; cvt.u32.u64 %0, t; }"
        : "=r"(a) : "l"(p));
    return a;
}
#define LDSM4(r0, r1, r2, r3, addr) \
    asm volatile("ldmatrix.sync.aligned.m8n8.x4.shared.b16 {%0,%1,%2,%3}, [%4];" \
                 : "=r"(r0), "=r"(r1), "=r"(r2), "=r"(r3) : "r"(addr))
#define MBARRIER_INIT(addr, cnt) \
    asm volatile("mbarrier.init.shared.b64 [%0], %1;" :: "r"(addr), "r"(cnt) : "memory")
#define MBARRIER_EXPECT_TX(addr, bytes) \
    asm volatile("mbarrier.arrive.expect_tx.shared.b64 _, [%0], %1;" \
                 :: "r"(addr), "r"((uint32_t)(bytes)) : "memory")
#define BULK_G2S(dst, src, bytes, mbar) \
    asm volatile("cp.async.bulk.shared::cta.global.mbarrier::complete_tx::bytes " \
                 "[%0], [%1], %2, [%3];" \
                 :: "r"(dst), "l"(src), "r"((uint32_t)(bytes)), "r"(mbar) : "memory")
#define MBARRIER_WAIT_PARITY(addr, par) do {                                      \
    uint32_t _m = (addr), _p = (par), _d;                                         \
    asm volatile("{\n\t.reg .pred p;\n\t"                                         \
        "mbarrier.try_wait.parity.acquire.cta.shared::cta.b64 p, [%1], %2;\n\t"   \
        "selp.b32 %0, 1, 0, p;\n\t}" : "=r"(_d) : "r"(_m), "r"(_p) : "memory");   \
    if (!_d) {                                                                    \
        asm volatile("{\n\t.reg .pred P1;\n\t"                                    \
            "WL_%=:\n\t"                                                          \
            "mbarrier.try_wait.parity.acquire.cta.shared::cta.b64 P1, [%0], %1, 0x989680;\n\t" \
            "@P1 bra.uni WD_%=;\n\tbra.uni WL_%=;\n\tWD_%=:\n\t}"                 \
            :: "r"(_m), "r"(_p) : "memory");                                      \
    }                                                                             \
} while (0)

__device__ __forceinline__ void mma_f16(float c[4],
                                        uint32_t a0, uint32_t a1, uint32_t a2, uint32_t a3,
                                        uint32_t b0, uint32_t b1) {
    asm volatile(
        "mma.sync.aligned.m16n8k16.row.col.f32.f16.f16.f32 "
        "{%0,%1,%2,%3}, {%4,%5,%6,%7}, {%8,%9}, {%0,%1,%2,%3};"
        : "+f"(c[0]), "+f"(c[1]), "+f"(c[2]), "+f"(c[3])
        : "r"(a0), "r"(a1), "r"(a2), "r"(a3), "r"(b0), "r"(b1));
}

// ---------------------------------------------------------------------------
// Prep: gZp[row] = [s1*x, s2*exp(1-dc)] fp16 at 528B pitch; fused row-norm.
// grid 128, block 256; one warp = one row.
// ---------------------------------------------------------------------------
__global__ void __launch_bounds__(256)
prep_kernel(const float* __restrict__ x, const float* __restrict__ dc,
            const float* __restrict__ ap) {
    const int g   = blockIdx.x * 256 + threadIdx.x;
    const int row = g >> 5;
    const int d   = (g & 31) * 4;
    const float a  = ap[0];
    const float s1 = sqrtf(2.0f * (1.0f - a));
    const float s2 = sqrtf(a);

    const float4 xv = *(const float4*)&x[row * DIM + d];
    const float4 dv = *(const float4*)&dc[row * DIM + d];

    __half zb[4] = { __float2half_rn(s1 * xv.x), __float2half_rn(s1 * xv.y),
                     __float2half_rn(s1 * xv.z), __float2half_rn(s1 * xv.w) };
    __half hb[4] = { __float2half_rn(s2 * __expf(1.0f - dv.x)),
                     __float2half_rn(s2 * __expf(1.0f - dv.y)),
                     __float2half_rn(s2 * __expf(1.0f - dv.z)),
                     __float2half_rn(s2 * __expf(1.0f - dv.w)) };

    const int ob = row * PITCH + d;
    *(uint2*)&gZp[ob]       = *(uint2*)zb;
    *(uint2*)&gZp[ob + DIM] = *(uint2*)hb;

    float s = xv.x * xv.x + xv.y * xv.y + xv.z * xv.z + xv.w * xv.w;
#pragma unroll
    for (int o = 16; o; o >>= 1) s += __shfl_down_sync(0xffffffffu, s, o);
    if ((threadIdx.x & 31) == 0) gC[row] = (1.0f - a) * s;
}

// ---------------------------------------------------------------------------
// Symmetric GEMM: only upper-triangular 64x64 tiles (136 CTAs, 1/SM, one
// wave).  512 threads = 16 warps in 4(m) x 4(n), warp tile 16x16
// (1 A-LDSM.x4 + 1 B-LDSM.x4 + 2 HMMA per k-step, register double-buffered).
// Full K=256 in smem via 2 bulk-DMA ops.  W = [-Zx|Zh]: A frags XOR-negated
// for k-steps 0..7.  Off-diagonal tiles also write the transposed block via
// an smem bounce (both store streams coalesced).
//   smem: A @0 (64*528=33792) | B @33792 ; 67584 B dynamic.
// ---------------------------------------------------------------------------
#define ROWB   528
#define OFF_B  33792
#define TILE_BYTES 33792
#define SMEM_BYTES 67584
#define TP 65   // transpose bounce pitch (floats)

__global__ void __launch_bounds__(512, 1)
gemm_kernel(float* __restrict__ out) {
    extern __shared__ __align__(16) char smem[];
    __shared__ __align__(8) uint64_t s_mbar;

    const int tid = threadIdx.x;
    const int wid = tid >> 5;
    const int lid = tid & 31;
    const int wm  = wid >> 2;          // 0..3 -> m offset wm*16
    const int wn  = wid & 3;           // 0..3 -> n offset wn*16

    // ---- decode upper-triangular tile (bi <= bj) ----
    int bi = 0, rem = blockIdx.x;
    while (rem >= 16 - bi) { rem -= 16 - bi; bi++; }
    const int bj = bi + rem;
    const int i0 = bi * 64;
    const int j0 = bj * 64;

    const uint32_t sb = smem_u32(smem);
    const uint32_t mb = smem_u32(&s_mbar);

    if (tid == 0) MBARRIER_INIT(mb, 1);
    __syncthreads();
    if (tid == 0) {
        MBARRIER_EXPECT_TX(mb, 2 * TILE_BYTES);
        BULK_G2S(sb,         gZp + (size_t)i0 * PITCH, TILE_BYTES, mb);
        BULK_G2S(sb + OFF_B, gZp + (size_t)j0 * PITCH, TILE_BYTES, mb);
    }

    // ---- per-lane ldmatrix base addresses ----
    const uint32_t arow = lid & 15;
    const uint32_t acol = (lid >> 4) * 16;            // bytes
    const uint32_t brow = (lid & 7) | (((lid >> 4) & 1) << 3);
    const uint32_t bcol = ((lid >> 3) & 1) * 16;
    const uint32_t aAd = sb + (wm * 16 + arow) * ROWB + acol;
    const uint32_t bAd = sb + OFF_B + (wn * 16 + brow) * ROWB + bcol;

    float acc[2][4] = {};
    uint32_t F[2][8];   // [set][ a0..3 | b0..3 ]

    auto ldf = [&](uint32_t* f, int ks) {
        const uint32_t ko = (uint32_t)ks * 32;
        LDSM4(f[0], f[1], f[2], f[3], aAd + ko);
        LDSM4(f[4], f[5], f[6], f[7], bAd + ko);
        if (ks < 8) {   // W's first K-half is -Z: negate A frags (packed fp16)
#pragma unroll
            for (int q = 0; q < 4; q++) f[q] ^= 0x80008000u;
        }
    };
    auto domma = [&](uint32_t* f) {
        mma_f16(acc[0], f[0], f[1], f[2], f[3], f[4], f[5]);
        mma_f16(acc[1], f[0], f[1], f[2], f[3], f[6], f[7]);
    };

    // ---- wait for DMA, 16 k-steps with register double-buffer ----
    MBARRIER_WAIT_PARITY(mb, 0);

    ldf(F[0], 0);
#pragma unroll
    for (int ks = 0; ks < 15; ks++) {
        ldf(F[(ks + 1) & 1], ks + 1);
        domma(F[ks & 1]);
    }
    domma(F[1]);

    // ---- epilogue ----
    const int g = lid >> 2;
    const int t = lid & 3;
    const int lia = wm * 16 + g;        // local A row
    const int lib = lia + 8;
    const int ia = i0 + lia;
    const int ib = i0 + lib;
    const float cia = gC[ia];
    const float cib = gC[ib];

    float res[2][4];
#pragma unroll
    for (int nf = 0; nf < 2; nf++) {
        const int j = j0 + wn * 16 + nf * 8 + t * 2;
        const float cj0 = gC[j];
        const float cj1 = gC[j + 1];
        const float* s = acc[nf];
        res[nf][0] = (ia == j)     ? 1.0f : __fdividef((float)DIM, cia + cj0 + s[0]);
        res[nf][1] = (ia == j + 1) ? 1.0f : __fdividef((float)DIM, cia + cj1 + s[1]);
        res[nf][2] = (ib == j)     ? 1.0f : __fdividef((float)DIM, cib + cj0 + s[2]);
        res[nf][3] = (ib == j + 1) ? 1.0f : __fdividef((float)DIM, cib + cj1 + s[3]);

        *(float2*)&out[ia * BSZ + j] = make_float2(res[nf][0], res[nf][1]);
        *(float2*)&out[ib * BSZ + j] = make_float2(res[nf][2], res[nf][3]);
    }

    // ---- transposed block for off-diagonal tiles (smem bounce) ----
    if (bi != bj) {
        float* T = (float*)smem;        // reuse A region: 64*65*4 = 16.6 KB
        __syncthreads();                // all LDSM reads of A done
#pragma unroll
        for (int nf = 0; nf < 2; nf++) {
            const int lj = wn * 16 + nf * 8 + t * 2;
            T[lia * TP + lj]     = res[nf][0];
            T[lia * TP + lj + 1] = res[nf][1];
            T[lib * TP + lj]     = res[nf][2];
            T[lib * TP + lj + 1] = res[nf][3];
        }
        __syncthreads();
        // coalesced store of the transpose: out[j0+r][i0+c] = T[c][r]
#pragma unroll
        for (int idx = tid; idx < 1024; idx += 512) {
            const int r  = idx >> 4;
            const int c4 = (idx & 15) * 4;
            float4 v;
            v.x = T[(c4 + 0) * TP + r];
            v.y = T[(c4 + 1) * TP + r];
            v.z = T[(c4 + 2) * TP + r];
            v.w = T[(c4 + 3) * TP + r];
            *(float4*)&out[(j0 + r) * BSZ + i0 + c4] = v;
        }
    }
}

// ---------------------------------------------------------------------------
extern "C" void kernel_launch(void* const* d_in, const int* in_sizes, int n_in,
                              void* d_out, int out_size) {
    const float* x  = (const float*)d_in[0];
    const float* dc = (const float*)d_in[1];
    const float* ap = (const float*)d_in[2];
    float* out = (float*)d_out;

    cudaFuncSetAttribute(gemm_kernel, cudaFuncAttributeMaxDynamicSharedMemorySize, SMEM_BYTES);

    prep_kernel<<<128, 256>>>(x, dc, ap);
    gemm_kernel<<<136, 512, SMEM_BYTES>>>(out);
}